// round 11
// baseline (speedup 1.0000x reference)
#include <cuda_runtime.h>
#include <cuda_fp16.h>
#include <cstdint>
#include <cstddef>

#define N_CTX 4096
#define D_MODEL 2048

// ---------------- scratch (__device__ globals; allocation-free) ----------------
__device__ __half g_Eh [(size_t)N_CTX * D_MODEL], g_El [(size_t)N_CTX * D_MODEL];
__device__ __half g_QKTh[(size_t)D_MODEL * D_MODEL], g_QKTl[(size_t)D_MODEL * D_MODEL];
__device__ __half g_OVTh[(size_t)D_MODEL * D_MODEL];
__device__ __half g_qh [(size_t)N_CTX * D_MODEL];
__device__ float  g_qf [(size_t)N_CTX * D_MODEL];
__device__ float  g_scores[(size_t)N_CTX * N_CTX];
__device__ __half g_cth[(size_t)N_CTX * D_MODEL];

// ---------------- PTX helpers (baseline ISA; no tcgen05) ----------------
__device__ __forceinline__ uint32_t s2u(const void* p) {
    uint32_t a;
    asm("{ .reg .u64 t; cvta.to.shared.u64 t, %1; cvt.u32.u64 %0, t; }" : "=r"(a) : "l"(p));
    return a;
}
__device__ __forceinline__ void cp16(uint32_t d, const void* s) {
    asm volatile("cp.async.cg.shared.global [%0], [%1], 16;" :: "r"(d), "l"(s) : "memory");
}
__device__ __forceinline__ void cp_commit() { asm volatile("cp.async.commit_group;" ::: "memory"); }
__device__ __forceinline__ void cp_wait1()  { asm volatile("cp.async.wait_group 1;" ::: "memory"); }
__device__ __forceinline__ void cp_wait0()  { asm volatile("cp.async.wait_group 0;" ::: "memory"); }
__device__ __forceinline__ void ldmx4(uint32_t& r0, uint32_t& r1, uint32_t& r2, uint32_t& r3, uint32_t a) {
    asm volatile("ldmatrix.sync.aligned.m8n8.x4.shared.b16 {%0,%1,%2,%3}, [%4];"
                 : "=r"(r0), "=r"(r1), "=r"(r2), "=r"(r3) : "r"(a));
}
__device__ __forceinline__ void mma16816(float* c, const uint32_t* a, uint32_t b0, uint32_t b1) {
    asm volatile(
        "mma.sync.aligned.m16n8k16.row.col.f32.f16.f16.f32 "
        "{%0,%1,%2,%3}, {%4,%5,%6,%7}, {%8,%9}, {%0,%1,%2,%3};"
        : "+f"(c[0]), "+f"(c[1]), "+f"(c[2]), "+f"(c[3])
        : "r"(a[0]), "r"(a[1]), "r"(a[2]), "r"(a[3]), "r"(b0), "r"(b1));
}

// ---------------- tile loader: 128 rows x 64 halves, XOR-swizzled 128B rows ----------------
__device__ __forceinline__ void ld_tile(uint32_t dst, const __half* __restrict__ src,
                                        int row0, int kbase, int K, int tid)
{
    const int r  = tid >> 1;
    const int cb = (tid & 1) * 4;
    const __half* g = src + (size_t)(row0 + r) * K + kbase;
    const uint32_t rowoff = dst + r * 128;
    const int rx = r & 7;
    #pragma unroll
    for (int c = 0; c < 4; c++) {
        const int ch = cb + c;
        cp16(rowoff + ((ch ^ rx) << 4), g + ch * 8);
    }
}

// TERMS==1: {Ah,Bh}  TERMS==3: {Ah,Al,Bh,Bl}
template<int TERMS>
__device__ __forceinline__ void ld_stage(uint32_t st,
    const __half* Ah, const __half* Al, const __half* Bh, const __half* Bl,
    int rowBase, int colBase, int kbase, int K, int tid)
{
    constexpr uint32_t AB = (TERMS >= 2) ? 32768u : 16384u;
    ld_tile(st, Ah, rowBase, kbase, K, tid);
    if (TERMS >= 2) ld_tile(st + 16384, Al, rowBase, kbase, K, tid);
    ld_tile(st + AB, Bh, colBase, kbase, K, tid);
    if (TERMS == 3) ld_tile(st + AB + 16384, Bl, colBase, kbase, K, tid);
    cp_commit();
}

// ---------------- split-fp16 HMMA GEMM: C[M,N] = A[M,K] @ B[N,K]^T ----------------
// TERMS: 3 = AhBh+AhBl+AlBh ; 1 = AhBh.
// MMA schedule: per k-step, ALL fragments are register-staged first, then MMAs
// issue term-by-term across all 16 accumulators -> same-acc reuse distance is
// 16 MMAs (was 2), eliminating RAW stalls on the tensor pipe.
// MODE: 0 dense, 1 causal tile-skip. SPLITOUT: 0 fp32 C ; 4 fp32 + hi fp16.
template<int MODE, int SPLITOUT, int TERMS>
__global__ __launch_bounds__(256) void gemm_hmma(
    const __half* __restrict__ Ah, const __half* __restrict__ Al,
    const __half* __restrict__ Bh, const __half* __restrict__ Bl,
    float* __restrict__ Cf, __half* __restrict__ Ch,
    int N, int K)
{
    constexpr uint32_t AB = (TERMS >= 2) ? 32768u : 16384u;
    constexpr uint32_t SB = (TERMS == 3) ? 65536u : 32768u;

    const int rowBase = blockIdx.y * 128;
    const int colBase = blockIdx.x * 128;
    if (MODE == 1 && colBase > rowBase) return;
    const int T = K >> 6;

    extern __shared__ char smraw[];
    const uint32_t sb = (s2u(smraw) + 127) & ~127u;
    const int tid = threadIdx.x;

    ld_stage<TERMS>(sb,      Ah, Al, Bh, Bl, rowBase, colBase, 0,  K, tid);
    ld_stage<TERMS>(sb + SB, Ah, Al, Bh, Bl, rowBase, colBase, 64, K, tid);

    const int warp = tid >> 5, lane = tid & 31;
    const int wM = (warp & 3) * 32;
    const int wN = (warp >> 2) * 64;

    float acc[2][8][4];
    #pragma unroll
    for (int mt = 0; mt < 2; mt++)
        #pragma unroll
        for (int n = 0; n < 8; n++)
            #pragma unroll
            for (int j = 0; j < 4; j++) acc[mt][n][j] = 0.f;

    const int aRowOff = (lane & 7) + (lane & 8);
    const int aChOff  = (lane >> 4) & 1;
    const int bRowOff = (lane & 7) + ((lane & 16) >> 1);
    const int bChOff  = (lane >> 3) & 1;

    for (int it = 0; it < T; it++) {
        if (it < T - 1) cp_wait1(); else cp_wait0();
        __syncthreads();
        if (it + 2 < T)
            ld_stage<TERMS>(sb + ((it + 2) % 3) * SB, Ah, Al, Bh, Bl,
                            rowBase, colBase, (it + 2) << 6, K, tid);

        const uint32_t stA = sb + (it % 3) * SB;
        const uint32_t stB = stA + AB;

        #pragma unroll
        for (int kk = 0; kk < 4; kk++) {
            // ---- register-stage all fragments for this k-step ----
            uint32_t aH[2][4], aL[2][4];
            #pragma unroll
            for (int mt = 0; mt < 2; mt++) {
                const int r  = wM + mt * 16 + aRowOff;
                const int ch = 2 * kk + aChOff;
                const uint32_t off = r * 128 + ((ch ^ (r & 7)) << 4);
                ldmx4(aH[mt][0], aH[mt][1], aH[mt][2], aH[mt][3], stA + off);
                if (TERMS >= 2)
                    ldmx4(aL[mt][0], aL[mt][1], aL[mt][2], aL[mt][3], stA + 16384 + off);
            }
            uint32_t bH[4][4], bL[4][4];
            #pragma unroll
            for (int nt = 0; nt < 4; nt++) {
                const int r  = wN + nt * 16 + bRowOff;
                const int ch = 2 * kk + bChOff;
                const uint32_t off = r * 128 + ((ch ^ (r & 7)) << 4);
                ldmx4(bH[nt][0], bH[nt][1], bH[nt][2], bH[nt][3], stB + off);
                if (TERMS == 3)
                    ldmx4(bL[nt][0], bL[nt][1], bL[nt][2], bL[nt][3], stB + 16384 + off);
            }

            // ---- term 1: Ah x Bh (16 independent MMAs) ----
            #pragma unroll
            for (int nt = 0; nt < 4; nt++)
                #pragma unroll
                for (int mt = 0; mt < 2; mt++) {
                    mma16816(acc[mt][nt * 2],     aH[mt], bH[nt][0], bH[nt][1]);
                    mma16816(acc[mt][nt * 2 + 1], aH[mt], bH[nt][2], bH[nt][3]);
                }
            // ---- term 2: Al x Bh ----
            if (TERMS >= 2)
                #pragma unroll
                for (int nt = 0; nt < 4; nt++)
                    #pragma unroll
                    for (int mt = 0; mt < 2; mt++) {
                        mma16816(acc[mt][nt * 2],     aL[mt], bH[nt][0], bH[nt][1]);
                        mma16816(acc[mt][nt * 2 + 1], aL[mt], bH[nt][2], bH[nt][3]);
                    }
            // ---- term 3: Ah x Bl ----
            if (TERMS == 3)
                #pragma unroll
                for (int nt = 0; nt < 4; nt++)
                    #pragma unroll
                    for (int mt = 0; mt < 2; mt++) {
                        mma16816(acc[mt][nt * 2],     aH[mt], bL[nt][0], bL[nt][1]);
                        mma16816(acc[mt][nt * 2 + 1], aH[mt], bL[nt][2], bL[nt][3]);
                    }
        }
    }

    // ---------------- epilogue ----------------
    const int g  = lane >> 2;
    const int t4 = lane & 3;
    #pragma unroll
    for (int mt = 0; mt < 2; mt++) {
        const int row0 = rowBase + wM + mt * 16 + g;
        #pragma unroll
        for (int n = 0; n < 8; n++) {
            const int col = colBase + wN + n * 8 + t4 * 2;
            *(float2*)(Cf + (size_t)row0 * N + col) =
                make_float2(acc[mt][n][0], acc[mt][n][1]);
            *(float2*)(Cf + (size_t)(row0 + 8) * N + col) =
                make_float2(acc[mt][n][2], acc[mt][n][3]);
            if (SPLITOUT == 4) {
                #pragma unroll
                for (int hrow = 0; hrow < 2; hrow++) {
                    const size_t o = (size_t)(row0 + hrow * 8) * N + col;
                    *(__half2*)(Ch + o) = __halves2half2(
                        __float2half(acc[mt][n][hrow * 2]),
                        __float2half(acc[mt][n][hrow * 2 + 1]));
                }
            }
        }
    }
}

// ---------------- fp32 -> (hi,lo) fp16 split ----------------
__global__ __launch_bounds__(256) void split_rm(const float* __restrict__ X,
                                                __half* __restrict__ H, __half* __restrict__ L, int n4)
{
    int i = blockIdx.x * 256 + threadIdx.x;
    if (i >= n4) return;
    float4 v = ((const float4*)X)[i];
    float vs[4] = {v.x, v.y, v.z, v.w};
    __half h[4], l[4];
    #pragma unroll
    for (int j = 0; j < 4; j++) {
        h[j] = __float2half(vs[j]);
        l[j] = __float2half(vs[j] - __half2float(h[j]));
    }
    ((__half2*)H)[2 * i]     = __halves2half2(h[0], h[1]);
    ((__half2*)H)[2 * i + 1] = __halves2half2(h[2], h[3]);
    ((__half2*)L)[2 * i]     = __halves2half2(l[0], l[1]);
    ((__half2*)L)[2 * i + 1] = __halves2half2(l[2], l[3]);
}

// ---------------- fp32 [R,C] -> transposed fp16 [C,R]; L optional ----------------
__global__ __launch_bounds__(256) void tsplit(const float* __restrict__ X,
                                              __half* __restrict__ H, __half* __restrict__ L, int R, int C)
{
    __shared__ float tile[32][33];
    const int tx = threadIdx.x, ty = threadIdx.y;
    const int c0 = blockIdx.x * 32, r0 = blockIdx.y * 32;
    #pragma unroll
    for (int i = 0; i < 32; i += 8)
        tile[ty + i][tx] = X[(size_t)(r0 + ty + i) * C + c0 + tx];
    __syncthreads();
    #pragma unroll
    for (int i = 0; i < 32; i += 8) {
        float v = tile[tx][ty + i];
        __half h = __float2half(v);
        size_t o = (size_t)(c0 + ty + i) * R + r0 + tx;
        H[o] = h;
        if (L) L[o] = __float2half(v - __half2float(h));
    }
}

// ---------------- fused: causal softmax + exact recompute + sparse ctx gather ----------------
#define RC_MARGIN 20.0f
#define RC_CAP 1024
__global__ __launch_bounds__(256) void softmax_ctx(const float* __restrict__ S,
                                                   const float* __restrict__ qf,
                                                   const float* __restrict__ emb,
                                                   __half* __restrict__ cth)
{
    __shared__ float buf[N_CTX];
    __shared__ float red[256];
    __shared__ int   list[RC_CAP];
    __shared__ float pw[RC_CAP];
    __shared__ int   cnt;
    const int i = blockIdx.x, t = threadIdx.x;
    const int n = i + 1;
    const float* row = S + (size_t)i * N_CTX;

    float m = -3.0e38f;
    for (int j = t; j < n; j += 256) { float v = row[j]; buf[j] = v; m = fmaxf(m, v); }
    red[t] = m;
    if (t == 0) cnt = 0;
    __syncthreads();
    for (int s2 = 128; s2 > 0; s2 >>= 1) {
        if (t < s2) red[t] = fmaxf(red[t], red[t + s2]);
        __syncthreads();
    }
    m = red[0];
    __syncthreads();

    for (int j = t; j < n; j += 256)
        if (buf[j] > m - RC_MARGIN) {
            int p = atomicAdd(&cnt, 1);
            if (p < RC_CAP) list[p] = j;
        }
    __syncthreads();
    const int nc = min(cnt, RC_CAP);

    const int warp = t >> 5, lane = t & 31;
    const float4* qp = (const float4*)(qf + (size_t)i * D_MODEL);
    for (int c = warp; c < nc; c += 8) {
        const int j = list[c];
        const float4* ep = (const float4*)(emb + (size_t)j * D_MODEL);
        float s = 0.f;
        #pragma unroll 4
        for (int k = lane; k < D_MODEL / 4; k += 32) {
            float4 a = qp[k], b = ep[k];
            s += a.x * b.x + a.y * b.y + a.z * b.z + a.w * b.w;
        }
        #pragma unroll
        for (int off = 16; off > 0; off >>= 1) s += __shfl_xor_sync(0xFFFFFFFFu, s, off);
        if (lane == 0) buf[j] = s;
    }
    __syncthreads();

    m = -3.0e38f;
    for (int j = t; j < n; j += 256) m = fmaxf(m, buf[j]);
    red[t] = m;
    __syncthreads();
    for (int s2 = 128; s2 > 0; s2 >>= 1) {
        if (t < s2) red[t] = fmaxf(red[t], red[t + s2]);
        __syncthreads();
    }
    m = red[0];
    __syncthreads();

    float s = 0.f;
    for (int j = t; j < n; j += 256) s += expf(buf[j] - m);
    red[t] = s;
    __syncthreads();
    for (int s2 = 128; s2 > 0; s2 >>= 1) {
        if (t < s2) red[t] += red[t + s2];
        __syncthreads();
    }
    const float inv = 1.0f / red[0];

    for (int c = t; c < nc; c += 256) pw[c] = expf(buf[list[c]] - m) * inv;
    __syncthreads();

    float acc[8];
    #pragma unroll
    for (int k = 0; k < 8; k++) acc[k] = 0.f;
    for (int c = 0; c < nc; c++) {
        const float p = pw[c];
        const float4* ep = (const float4*)(emb + (size_t)list[c] * D_MODEL + t * 8);
        float4 a = ep[0], b = ep[1];
        acc[0] += p * a.x; acc[1] += p * a.y; acc[2] += p * a.z; acc[3] += p * a.w;
        acc[4] += p * b.x; acc[5] += p * b.y; acc[6] += p * b.z; acc[7] += p * b.w;
    }
    __half2* dst = (__half2*)(cth + (size_t)i * D_MODEL + t * 8);
    #pragma unroll
    for (int k = 0; k < 4; k++)
        dst[k] = __halves2half2(__float2half(acc[2 * k]), __float2half(acc[2 * k + 1]));
}

// ---------------------------------------------------------------------------
extern "C" void kernel_launch(void* const* d_in, const int* in_sizes, int n_in,
                              void* d_out, int out_size)
{
    const float* emb = (const float*)d_in[0];   // [4096, 2048]
    const float* qk  = (const float*)d_in[1];   // [2048, 2048]
    const float* ov  = (const float*)d_in[2];   // [2048, 2048]
    float* out = (float*)d_out;                 // [4096, 2048]

    __half *Eh, *El, *QKTh, *QKTl, *OVTh, *qh, *cth;
    float *scores, *qf;
    cudaGetSymbolAddress((void**)&Eh, g_Eh);     cudaGetSymbolAddress((void**)&El, g_El);
    cudaGetSymbolAddress((void**)&QKTh, g_QKTh); cudaGetSymbolAddress((void**)&QKTl, g_QKTl);
    cudaGetSymbolAddress((void**)&OVTh, g_OVTh);
    cudaGetSymbolAddress((void**)&qh, g_qh);
    cudaGetSymbolAddress((void**)&cth, g_cth);
    cudaGetSymbolAddress((void**)&scores, g_scores);
    cudaGetSymbolAddress((void**)&qf, g_qf);

    const int SMEM3 = 3 * 65536 + 128;
    const int SMEM1 = 3 * 32768 + 128;
    cudaFuncSetAttribute(gemm_hmma<0,4,3>, cudaFuncAttributeMaxDynamicSharedMemorySize, SMEM3);
    cudaFuncSetAttribute(gemm_hmma<1,0,1>, cudaFuncAttributeMaxDynamicSharedMemorySize, SMEM1);
    cudaFuncSetAttribute(gemm_hmma<0,0,1>, cudaFuncAttributeMaxDynamicSharedMemorySize, SMEM1);

    // operand prep
    split_rm<<<(N_CTX * D_MODEL / 4 + 255) / 256, 256>>>(emb, Eh, El, N_CTX * D_MODEL / 4);
    tsplit<<<dim3(D_MODEL / 32, D_MODEL / 32), dim3(32, 8)>>>(qk, QKTh, QKTl, D_MODEL, D_MODEL);
    tsplit<<<dim3(D_MODEL / 32, D_MODEL / 32), dim3(32, 8)>>>(ov, OVTh, nullptr, D_MODEL, D_MODEL);

    // 1) q = E @ QK : 3-term, fp32 + hi fp16 out
    gemm_hmma<0,4,3><<<dim3(D_MODEL / 128, N_CTX / 128), 256, SMEM3>>>(
        Eh, El, QKTh, QKTl, qf, qh, D_MODEL, D_MODEL);
    // 2) scores ~= q @ E^T : 1-term approx, causal tile-skip
    gemm_hmma<1,0,1><<<dim3(N_CTX / 128, N_CTX / 128), 256, SMEM1>>>(
        qh, nullptr, Eh, nullptr, scores, nullptr, N_CTX, D_MODEL);
    // 3) fused softmax + exact recompute + sparse ctx gather -> cth fp16
    softmax_ctx<<<N_CTX, 256>>>(scores, qf, emb, cth);
    // 4) out = ctx @ OV : 1-term, fp32 out
    gemm_hmma<0,0,1><<<dim3(D_MODEL / 128, N_CTX / 128), 256, SMEM1>>>(
        cth, nullptr, OVTh, nullptr, out, nullptr, D_MODEL, D_MODEL);
}